// round 1
// baseline (speedup 1.0000x reference)
#include <cuda_runtime.h>
#include <math.h>

#define D_MODEL 1024
#define DHEAD   64
#define NHEADS  16
#define DHID    4096
#define BATCH   2
#define SEQ     2048
#define MROWS   (BATCH*SEQ)   // 4096
#define LN_EPS  1e-5f

// ---------------- scratch (device globals; no allocations allowed) ----------
__device__ float g_Q  [MROWS*D_MODEL];
__device__ float g_K  [MROWS*D_MODEL];
__device__ float g_V  [MROWS*D_MODEL];
__device__ float g_CTX[MROWS*D_MODEL];
__device__ float g_PRJ[MROWS*D_MODEL];
__device__ float g_X1 [MROWS*D_MODEL];
__device__ float g_H  [(size_t)MROWS*DHID];
__device__ float g_T  [MROWS*D_MODEL];

// ---------------- helpers ---------------------------------------------------
__device__ __forceinline__ float gelu_exact(float x) {
    return 0.5f * x * (1.0f + erff(x * 0.70710678118654752f));
}

// ---------------- tiled fp32 GEMM: C[M,N] = A[M,K] @ B[K,N] (+bias, +act) ----
// BM=BN=64, BK=16, 256 threads, 4x4 accum per thread. All dims multiples of 64/16.
// act: 0 = none, 1 = exact GELU
__global__ void gemm64_kernel(const float* __restrict__ A, const float* __restrict__ B,
                              const float* __restrict__ bias, float* __restrict__ C,
                              int M, int N, int K, int act)
{
    __shared__ float As[16][68];   // [k][m], padded
    __shared__ float Bs[16][64];   // [k][n]

    const int tid  = threadIdx.x;
    const int row0 = blockIdx.y * 64;
    const int col0 = blockIdx.x * 64;
    const int tx = tid & 15;       // 0..15 -> 4 cols each
    const int ty = tid >> 4;       // 0..15 -> 4 rows each

    // A load: each thread one float4; ar = row-in-tile, ak = k offset
    const int ar = tid >> 2;            // 0..63
    const int ak = (tid & 3) << 2;      // 0,4,8,12
    // B load: each thread one float4; bkr = k row, bn = col offset
    const int bkr = tid >> 4;           // 0..15
    const int bn  = (tid & 15) << 2;    // 0..60

    const float* Aptr = A + (size_t)(row0 + ar) * K + ak;
    const float* Bptr = B + (size_t)bkr * N + col0 + bn;

    float acc[4][4];
    #pragma unroll
    for (int i = 0; i < 4; i++)
        #pragma unroll
        for (int j = 0; j < 4; j++) acc[i][j] = 0.0f;

    for (int k0 = 0; k0 < K; k0 += 16) {
        float4 a4 = *(const float4*)(Aptr + k0);
        As[ak + 0][ar] = a4.x;
        As[ak + 1][ar] = a4.y;
        As[ak + 2][ar] = a4.z;
        As[ak + 3][ar] = a4.w;
        *(float4*)&Bs[bkr][bn] = *(const float4*)(Bptr + (size_t)k0 * N);
        __syncthreads();

        #pragma unroll
        for (int k = 0; k < 16; k++) {
            float4 a = *(const float4*)&As[k][ty << 2];
            float4 b = *(const float4*)&Bs[k][tx << 2];
            acc[0][0] += a.x * b.x; acc[0][1] += a.x * b.y; acc[0][2] += a.x * b.z; acc[0][3] += a.x * b.w;
            acc[1][0] += a.y * b.x; acc[1][1] += a.y * b.y; acc[1][2] += a.y * b.z; acc[1][3] += a.y * b.w;
            acc[2][0] += a.z * b.x; acc[2][1] += a.z * b.y; acc[2][2] += a.z * b.z; acc[2][3] += a.z * b.w;
            acc[3][0] += a.w * b.x; acc[3][1] += a.w * b.y; acc[3][2] += a.w * b.z; acc[3][3] += a.w * b.w;
        }
        __syncthreads();
    }

    const int cbase = col0 + (tx << 2);
    float4 bv = make_float4(0.f, 0.f, 0.f, 0.f);
    if (bias) bv = *(const float4*)(bias + cbase);

    #pragma unroll
    for (int i = 0; i < 4; i++) {
        const int r = row0 + (ty << 2) + i;
        float4 c;
        c.x = acc[i][0] + bv.x;
        c.y = acc[i][1] + bv.y;
        c.z = acc[i][2] + bv.z;
        c.w = acc[i][3] + bv.w;
        if (act == 1) {
            c.x = gelu_exact(c.x); c.y = gelu_exact(c.y);
            c.z = gelu_exact(c.z); c.w = gelu_exact(c.w);
        }
        *(float4*)&C[(size_t)r * N + cbase] = c;
    }
}

// ---------------- flash-style causal attention -------------------------------
// grid: (SEQ/64, BATCH*NHEADS), block: 64 threads. One thread = one query row.
__global__ void attn_kernel(const float* __restrict__ Qp, const float* __restrict__ Kp,
                            const float* __restrict__ Vp, float* __restrict__ O)
{
    const int qt  = blockIdx.x;           // query tile (0..31)
    const int bh  = blockIdx.y;           // 0..31
    const int b   = bh >> 4;
    const int h   = bh & 15;
    const int tid = threadIdx.x;          // 0..63
    const int qi  = qt * 64 + tid;        // global query index in sequence

    const size_t qoff = ((size_t)(b * SEQ + qi)) * D_MODEL + h * 64;

    float q[64];
    #pragma unroll
    for (int d4 = 0; d4 < 16; d4++) {
        float4 t = *(const float4*)(Qp + qoff + d4 * 4);
        q[d4*4+0] = t.x * 0.125f;  // 1/sqrt(64)
        q[d4*4+1] = t.y * 0.125f;
        q[d4*4+2] = t.z * 0.125f;
        q[d4*4+3] = t.w * 0.125f;
    }

    float acc[64];
    #pragma unroll
    for (int d = 0; d < 64; d++) acc[d] = 0.0f;
    float mrun = -1e30f, l = 0.0f;

    __shared__ float Ks[64][64];
    __shared__ float Vs[64][64];
    __shared__ float Ps[64][65];

    const size_t base = ((size_t)b * SEQ) * D_MODEL + h * 64;

    for (int kt = 0; kt <= qt; kt++) {
        // cooperative coalesced tile load: 64x64 floats of K and V
        #pragma unroll
        for (int it = 0; it < 16; it++) {
            const int idx = it * 64 + tid;        // 0..1023
            const int r   = idx >> 4;
            const int c4  = (idx & 15) << 2;
            const size_t off = base + (size_t)(kt * 64 + r) * D_MODEL + c4;
            *(float4*)&Ks[r][c4] = *(const float4*)(Kp + off);
            *(float4*)&Vs[r][c4] = *(const float4*)(Vp + off);
        }
        __syncthreads();

        const bool diag = (kt == qt);
        float tmax = -1e30f;
        for (int kk = 0; kk < 64; kk++) {
            float s = 0.0f;
            #pragma unroll
            for (int d4 = 0; d4 < 16; d4++) {
                float4 kv = *(const float4*)&Ks[kk][d4 << 2];
                s += q[d4*4+0] * kv.x + q[d4*4+1] * kv.y
                   + q[d4*4+2] * kv.z + q[d4*4+3] * kv.w;
            }
            if (diag && kk > tid) s = -1e30f;
            Ps[tid][kk] = s;
            tmax = fmaxf(tmax, s);
        }

        const float mnew = fmaxf(mrun, tmax);
        const float corr = __expf(mrun - mnew);
        l *= corr;
        #pragma unroll
        for (int d = 0; d < 64; d++) acc[d] *= corr;

        for (int kk = 0; kk < 64; kk++) {
            const float p = __expf(Ps[tid][kk] - mnew);
            l += p;
            #pragma unroll
            for (int d4 = 0; d4 < 16; d4++) {
                float4 vv = *(const float4*)&Vs[kk][d4 << 2];
                acc[d4*4+0] += p * vv.x;
                acc[d4*4+1] += p * vv.y;
                acc[d4*4+2] += p * vv.z;
                acc[d4*4+3] += p * vv.w;
            }
        }
        mrun = mnew;
        __syncthreads();
    }

    const float inv = 1.0f / l;
    #pragma unroll
    for (int d4 = 0; d4 < 16; d4++) {
        float4 o;
        o.x = acc[d4*4+0] * inv;
        o.y = acc[d4*4+1] * inv;
        o.z = acc[d4*4+2] * inv;
        o.w = acc[d4*4+3] * inv;
        *(float4*)(O + qoff + d4 * 4) = o;
    }
}

// ---------------- fused LayerNorm + residual add -----------------------------
// out[row] = resid[row] + LN(inp[row]) * g + b     (block = 256 threads, 1 row)
__global__ void ln_res_kernel(const float* __restrict__ inp, const float* __restrict__ resid,
                              const float* __restrict__ gam, const float* __restrict__ bet,
                              float* __restrict__ out)
{
    const int row = blockIdx.x;
    const int tid = threadIdx.x;
    const float* v = inp + (size_t)row * D_MODEL;

    float vals[4];
    float s = 0.0f;
    #pragma unroll
    for (int i = 0; i < 4; i++) { vals[i] = v[tid + 256 * i]; s += vals[i]; }

    __shared__ float red1[8];
    __shared__ float red2[8];
    const int lane = tid & 31, w = tid >> 5;

    #pragma unroll
    for (int o = 16; o > 0; o >>= 1) s += __shfl_xor_sync(0xffffffffu, s, o);
    if (lane == 0) red1[w] = s;
    __syncthreads();
    float mu = 0.0f;
    #pragma unroll
    for (int i = 0; i < 8; i++) mu += red1[i];
    mu *= (1.0f / D_MODEL);

    float vs = 0.0f;
    #pragma unroll
    for (int i = 0; i < 4; i++) { float d = vals[i] - mu; vs += d * d; }
    #pragma unroll
    for (int o = 16; o > 0; o >>= 1) vs += __shfl_xor_sync(0xffffffffu, vs, o);
    if (lane == 0) red2[w] = vs;
    __syncthreads();
    float var = 0.0f;
    #pragma unroll
    for (int i = 0; i < 8; i++) var += red2[i];
    var *= (1.0f / D_MODEL);
    const float rs = rsqrtf(var + LN_EPS);

    #pragma unroll
    for (int i = 0; i < 4; i++) {
        const int idx = tid + 256 * i;
        const size_t off = (size_t)row * D_MODEL + idx;
        out[off] = resid[off] + (vals[i] - mu) * rs * gam[idx] + bet[idx];
    }
}

// ---------------- launch -----------------------------------------------------
extern "C" void kernel_launch(void* const* d_in, const int* in_sizes, int n_in,
                              void* d_out, int out_size)
{
    const float* x     = (const float*)d_in[0];
    const float* wq    = (const float*)d_in[1];
    const float* bq    = (const float*)d_in[2];
    const float* wk    = (const float*)d_in[3];
    const float* bk    = (const float*)d_in[4];
    const float* wv    = (const float*)d_in[5];
    const float* bv    = (const float*)d_in[6];
    const float* wo    = (const float*)d_in[7];
    const float* ln1_g = (const float*)d_in[8];
    const float* ln1_b = (const float*)d_in[9];
    const float* w1    = (const float*)d_in[10];
    const float* b1    = (const float*)d_in[11];
    const float* w2    = (const float*)d_in[12];
    const float* ln2_g = (const float*)d_in[13];
    const float* ln2_b = (const float*)d_in[14];
    float* out = (float*)d_out;

    void *pQ, *pK, *pV, *pCTX, *pPRJ, *pX1, *pH, *pT;
    cudaGetSymbolAddress(&pQ,   g_Q);
    cudaGetSymbolAddress(&pK,   g_K);
    cudaGetSymbolAddress(&pV,   g_V);
    cudaGetSymbolAddress(&pCTX, g_CTX);
    cudaGetSymbolAddress(&pPRJ, g_PRJ);
    cudaGetSymbolAddress(&pX1,  g_X1);
    cudaGetSymbolAddress(&pH,   g_H);
    cudaGetSymbolAddress(&pT,   g_T);
    float* Q   = (float*)pQ;   float* K   = (float*)pK;  float* V  = (float*)pV;
    float* CTX = (float*)pCTX; float* PRJ = (float*)pPRJ;
    float* X1  = (float*)pX1;  float* H   = (float*)pH;  float* T  = (float*)pT;

    const dim3 blk(256);
    const dim3 g1024(D_MODEL / 64, MROWS / 64);   // N=1024
    const dim3 g4096(DHID / 64,   MROWS / 64);    // N=4096

    // QKV projections
    gemm64_kernel<<<g1024, blk>>>(x, wq, bq, Q, MROWS, D_MODEL, D_MODEL, 0);
    gemm64_kernel<<<g1024, blk>>>(x, wk, bk, K, MROWS, D_MODEL, D_MODEL, 0);
    gemm64_kernel<<<g1024, blk>>>(x, wv, bv, V, MROWS, D_MODEL, D_MODEL, 0);

    // causal multi-head attention -> CTX (already merged layout [B,S,H*dv])
    attn_kernel<<<dim3(SEQ / 64, BATCH * NHEADS), 64>>>(Q, K, V, CTX);

    // out projection + LN + residual
    gemm64_kernel<<<g1024, blk>>>(CTX, wo, nullptr, PRJ, MROWS, D_MODEL, D_MODEL, 0);
    ln_res_kernel<<<MROWS, 256>>>(PRJ, x, ln1_g, ln1_b, X1);

    // FFN
    gemm64_kernel<<<g4096, blk>>>(X1, w1, b1, H, MROWS, DHID, D_MODEL, 1);
    gemm64_kernel<<<g1024, blk>>>(H, w2, nullptr, T, MROWS, D_MODEL, DHID, 0);
    ln_res_kernel<<<MROWS, 256>>>(T, X1, ln2_g, ln2_b, out);
}

// round 5
// speedup vs baseline: 2.0844x; 2.0844x over previous
#include <cuda_runtime.h>
#include <math.h>
#include <cstdint>

#define D_MODEL 1024
#define DHEAD   64
#define NHEADS  16
#define DHID    4096
#define BATCH   2
#define SEQ     2048
#define MROWS   (BATCH*SEQ)   // 4096
#define LN_EPS  1e-5f

// ---------------- scratch (device globals; no allocations allowed) ----------
__device__ float g_Q  [MROWS*D_MODEL];
__device__ float g_K  [MROWS*D_MODEL];
__device__ float g_V  [MROWS*D_MODEL];
__device__ float g_CTX[MROWS*D_MODEL];
__device__ float g_PRJ[MROWS*D_MODEL];
__device__ float g_X1 [MROWS*D_MODEL];
__device__ float g_X1r[MROWS*D_MODEL];
__device__ float g_T  [MROWS*D_MODEL];
__device__ float g_Xr [MROWS*D_MODEL];
__device__ float g_H  [(size_t)MROWS*DHID];
__device__ float g_WTq[D_MODEL*D_MODEL];
__device__ float g_WTk[D_MODEL*D_MODEL];
__device__ float g_WTv[D_MODEL*D_MODEL];
__device__ float g_WTo[D_MODEL*D_MODEL];
__device__ float g_WT1[(size_t)DHID*D_MODEL];
__device__ float g_WT2[(size_t)D_MODEL*DHID];

// ---------------- small asm helpers ------------------------------------------
__device__ __forceinline__ uint32_t smem_u32(const void* p) {
    uint32_t a;
    asm("{ .reg .u64 t; cvta.to.shared.u64 t, %1; cvt.u32.u64 %0, t; }" : "=r"(a) : "l"(p));
    return a;
}
__device__ __forceinline__ void cp_async16(uint32_t s, const void* g) {
    asm volatile("cp.async.cg.shared.global [%0], [%1], 16;" :: "r"(s), "l"(g));
}
#define CP_COMMIT() asm volatile("cp.async.commit_group;")
#define CP_WAIT(N)  asm volatile("cp.async.wait_group %0;" :: "n"(N))

__device__ __forceinline__ float tf32r(float x) {
    float y;
    asm("cvt.rna.tf32.f32 %0, %1;" : "=f"(y) : "f"(x));
    return y;
}
__device__ __forceinline__ void mma_tf32(float* d, const float* a, const float* b) {
    asm volatile(
        "mma.sync.aligned.m16n8k8.row.col.f32.tf32.tf32.f32 "
        "{%0,%1,%2,%3}, {%4,%5,%6,%7}, {%8,%9}, {%0,%1,%2,%3};"
        : "+f"(d[0]), "+f"(d[1]), "+f"(d[2]), "+f"(d[3])
        : "r"(__float_as_uint(a[0])), "r"(__float_as_uint(a[1])),
          "r"(__float_as_uint(a[2])), "r"(__float_as_uint(a[3])),
          "r"(__float_as_uint(b[0])), "r"(__float_as_uint(b[1])));
}

__device__ __forceinline__ float gelu_exact(float x) {
    return 0.5f * x * (1.0f + erff(x * 0.70710678118654752f));
}

// ---------------- tf32 mma.sync GEMM ------------------------------------------
// C[M,N] = A[M,K] @ BT[N,K]^T   (A, BT fp32 holding tf32-rounded values)
// 128x128 tile, BK=16, 256 threads (2x4 warps, 64x32 per warp), cp.async
// double-buffered. Smem rows padded to 20 floats -> conflict-free fragment LDS.
#define BK   16
#define SROW 20   // padded row length in floats

__global__ __launch_bounds__(256, 2)
void gemm_tc(const float* __restrict__ A, const float* __restrict__ BT,
             const float* __restrict__ bias, float* __restrict__ Cf,
             int M, int N, int K, int act, int round_out)
{
    __shared__ __align__(16) float As[2][128 * SROW];
    __shared__ __align__(16) float Bs[2][128 * SROW];

    const int tid  = threadIdx.x;
    const int wid  = tid >> 5;
    const int lane = tid & 31;
    const int wm   = wid >> 2;            // 0..1  (64 rows each)
    const int wn   = wid & 3;             // 0..3  (32 cols each)
    const int row0 = blockIdx.y * 128;
    const int col0 = blockIdx.x * 128;

    const uint32_t sA[2] = { smem_u32(As[0]), smem_u32(As[1]) };
    const uint32_t sB[2] = { smem_u32(Bs[0]), smem_u32(Bs[1]) };

    const int fr = lane >> 2;      // 0..7  (fragment row group)
    const int fc = lane & 3;       // 0..3  (fragment k)

    float acc[4][4][4];
    #pragma unroll
    for (int i = 0; i < 4; i++)
        #pragma unroll
        for (int j = 0; j < 4; j++)
            #pragma unroll
            for (int q = 0; q < 4; q++) acc[i][j][q] = 0.0f;

    const int nChunks = K / BK;

    // async chunk loader: 128 rows x 16 floats for A and BT
    auto load_chunk = [&](int c, int st) {
        const int k0 = c * BK;
        #pragma unroll
        for (int i = 0; i < 2; i++) {
            const int u  = tid + i * 256;       // 0..511
            const int r  = u >> 2;              // 0..127
            const int kc = (u & 3) * 4;         // 0,4,8,12
            cp_async16(sA[st] + (uint32_t)(r * SROW + kc) * 4,
                       A  + (size_t)(row0 + r) * K + k0 + kc);
            cp_async16(sB[st] + (uint32_t)(r * SROW + kc) * 4,
                       BT + (size_t)(col0 + r) * K + k0 + kc);
        }
        CP_COMMIT();
    };

    load_chunk(0, 0);

    for (int c = 0; c < nChunks; c++) {
        const int st = c & 1;
        if (c + 1 < nChunks) {
            load_chunk(c + 1, st ^ 1);
            CP_WAIT(1);
        } else {
            CP_WAIT(0);
        }
        __syncthreads();

        const float* Ab = As[st];
        const float* Bb = Bs[st];

        #pragma unroll
        for (int ks = 0; ks < 2; ks++) {
            const int kk = ks * 8 + fc;
            float af[4][4], bfr[4][2];
            #pragma unroll
            for (int mt = 0; mt < 4; mt++) {
                const int r = wm * 64 + mt * 16 + fr;
                af[mt][0] = Ab[r * SROW + kk];
                af[mt][1] = Ab[(r + 8) * SROW + kk];
                af[mt][2] = Ab[r * SROW + kk + 4];
                af[mt][3] = Ab[(r + 8) * SROW + kk + 4];
            }
            #pragma unroll
            for (int nt = 0; nt < 4; nt++) {
                const int n = wn * 32 + nt * 8 + fr;
                bfr[nt][0] = Bb[n * SROW + ks * 8 + fc];
                bfr[nt][1] = Bb[n * SROW + ks * 8 + fc + 4];
            }
            #pragma unroll
            for (int mt = 0; mt < 4; mt++)
                #pragma unroll
                for (int nt = 0; nt < 4; nt++)
                    mma_tf32(acc[mt][nt], af[mt], bfr[nt]);
        }
        __syncthreads();
    }

    // ---- epilogue ----
    const int gr = lane >> 2;
    const int gc = (lane & 3) * 2;
    #pragma unroll
    for (int mt = 0; mt < 4; mt++) {
        #pragma unroll
        for (int nt = 0; nt < 4; nt++) {
            const int rA = row0 + wm * 64 + mt * 16 + gr;
            const int cA = col0 + wn * 32 + nt * 8 + gc;
            float b0 = 0.f, b1 = 0.f;
            if (bias) { b0 = bias[cA]; b1 = bias[cA + 1]; }
            float v00 = acc[mt][nt][0] + b0, v01 = acc[mt][nt][1] + b1;
            float v10 = acc[mt][nt][2] + b0, v11 = acc[mt][nt][3] + b1;
            if (act == 1) {
                v00 = gelu_exact(v00); v01 = gelu_exact(v01);
                v10 = gelu_exact(v10); v11 = gelu_exact(v11);
            }
            if (round_out) {
                v00 = tf32r(v00); v01 = tf32r(v01);
                v10 = tf32r(v10); v11 = tf32r(v11);
            }
            *(float2*)&Cf[(size_t)rA * N + cA]       = make_float2(v00, v01);
            *(float2*)&Cf[(size_t)(rA + 8) * N + cA] = make_float2(v10, v11);
        }
    }
}

// ---------------- fp32 -> tf32-rounded fp32 ----------------------------------
__global__ void round_tf32(const float* __restrict__ in, float* __restrict__ out, int n)
{
    const int i = (blockIdx.x * blockDim.x + threadIdx.x) * 4;
    if (i < n) {
        float4 v = *(const float4*)(in + i);
        v.x = tf32r(v.x); v.y = tf32r(v.y); v.z = tf32r(v.z); v.w = tf32r(v.w);
        *(float4*)(out + i) = v;
    }
}

// ---------------- transpose + tf32 round: W[K,N] f32 -> WT[N,K] --------------
__global__ void transpose_rnd(const float* __restrict__ W, float* __restrict__ WT,
                              int Kd, int Nd)
{
    __shared__ float t[32][33];
    const int bx = blockIdx.x * 32;  // N offset
    const int by = blockIdx.y * 32;  // K offset
    const int tx = threadIdx.x, ty = threadIdx.y;
    #pragma unroll
    for (int i = ty; i < 32; i += 8)
        t[i][tx] = W[(size_t)(by + i) * Nd + bx + tx];
    __syncthreads();
    #pragma unroll
    for (int i = ty; i < 32; i += 8)
        WT[(size_t)(bx + i) * Kd + by + tx] = tf32r(t[tx][i]);
}

// ---------------- flash-style causal attention (fp32) ------------------------
// Output stores are tf32-rounded (CTX only feeds the WO GEMM).
__global__ void attn_kernel(const float* __restrict__ Qp, const float* __restrict__ Kp,
                            const float* __restrict__ Vp, float* __restrict__ O)
{
    const int qt  = blockIdx.x;
    const int bh  = blockIdx.y;
    const int b   = bh >> 4;
    const int h   = bh & 15;
    const int tid = threadIdx.x;
    const int qi  = qt * 64 + tid;

    const size_t qoff = ((size_t)(b * SEQ + qi)) * D_MODEL + h * 64;

    float q[64];
    #pragma unroll
    for (int d4 = 0; d4 < 16; d4++) {
        float4 t = *(const float4*)(Qp + qoff + d4 * 4);
        q[d4*4+0] = t.x * 0.125f;
        q[d4*4+1] = t.y * 0.125f;
        q[d4*4+2] = t.z * 0.125f;
        q[d4*4+3] = t.w * 0.125f;
    }

    float acc[64];
    #pragma unroll
    for (int d = 0; d < 64; d++) acc[d] = 0.0f;
    float mrun = -1e30f, l = 0.0f;

    __shared__ float Ks[64][64];
    __shared__ float Vs[64][64];
    __shared__ float Ps[64][65];

    const size_t base = ((size_t)b * SEQ) * D_MODEL + h * 64;

    for (int kt = 0; kt <= qt; kt++) {
        #pragma unroll
        for (int it = 0; it < 16; it++) {
            const int idx = it * 64 + tid;
            const int r   = idx >> 4;
            const int c4  = (idx & 15) << 2;
            const size_t off = base + (size_t)(kt * 64 + r) * D_MODEL + c4;
            *(float4*)&Ks[r][c4] = *(const float4*)(Kp + off);
            *(float4*)&Vs[r][c4] = *(const float4*)(Vp + off);
        }
        __syncthreads();

        const bool diag = (kt == qt);
        float tmax = -1e30f;
        for (int kk = 0; kk < 64; kk++) {
            float s = 0.0f;
            #pragma unroll
            for (int d4 = 0; d4 < 16; d4++) {
                float4 kv = *(const float4*)&Ks[kk][d4 << 2];
                s += q[d4*4+0] * kv.x + q[d4*4+1] * kv.y
                   + q[d4*4+2] * kv.z + q[d4*4+3] * kv.w;
            }
            if (diag && kk > tid) s = -1e30f;
            Ps[tid][kk] = s;
            tmax = fmaxf(tmax, s);
        }

        const float mnew = fmaxf(mrun, tmax);
        const float corr = __expf(mrun - mnew);
        l *= corr;
        #pragma unroll
        for (int d = 0; d < 64; d++) acc[d] *= corr;

        for (int kk = 0; kk < 64; kk++) {
            const float p = __expf(Ps[tid][kk] - mnew);
            l += p;
            #pragma unroll
            for (int d4 = 0; d4 < 16; d4++) {
                float4 vv = *(const float4*)&Vs[kk][d4 << 2];
                acc[d4*4+0] += p * vv.x;
                acc[d4*4+1] += p * vv.y;
                acc[d4*4+2] += p * vv.z;
                acc[d4*4+3] += p * vv.w;
            }
        }
        mrun = mnew;
        __syncthreads();
    }

    const float inv = 1.0f / l;
    #pragma unroll
    for (int d4 = 0; d4 < 16; d4++) {
        float4 o;
        o.x = tf32r(acc[d4*4+0] * inv);
        o.y = tf32r(acc[d4*4+1] * inv);
        o.z = tf32r(acc[d4*4+2] * inv);
        o.w = tf32r(acc[d4*4+3] * inv);
        *(float4*)(O + qoff + d4 * 4) = o;
    }
}

// ---------------- fused LayerNorm + residual add -----------------------------
// out = resid + LN(inp)*g + b (fp32).  out_r (optional) = tf32-rounded copy.
__global__ void ln_res_kernel(const float* __restrict__ inp, const float* __restrict__ resid,
                              const float* __restrict__ gam, const float* __restrict__ bet,
                              float* __restrict__ out, float* __restrict__ out_r)
{
    const int row = blockIdx.x;
    const int tid = threadIdx.x;
    const float* v = inp + (size_t)row * D_MODEL;

    float vals[4];
    float s = 0.0f;
    #pragma unroll
    for (int i = 0; i < 4; i++) { vals[i] = v[tid + 256 * i]; s += vals[i]; }

    __shared__ float red1[8];
    __shared__ float red2[8];
    const int lane = tid & 31, w = tid >> 5;

    #pragma unroll
    for (int o = 16; o > 0; o >>= 1) s += __shfl_xor_sync(0xffffffffu, s, o);
    if (lane == 0) red1[w] = s;
    __syncthreads();
    float mu = 0.0f;
    #pragma unroll
    for (int i = 0; i < 8; i++) mu += red1[i];
    mu *= (1.0f / D_MODEL);

    float vs = 0.0f;
    #pragma unroll
    for (int i = 0; i < 4; i++) { float d = vals[i] - mu; vs += d * d; }
    #pragma unroll
    for (int o = 16; o > 0; o >>= 1) vs += __shfl_xor_sync(0xffffffffu, vs, o);
    if (lane == 0) red2[w] = vs;
    __syncthreads();
    float var = 0.0f;
    #pragma unroll
    for (int i = 0; i < 8; i++) var += red2[i];
    var *= (1.0f / D_MODEL);
    const float rs = rsqrtf(var + LN_EPS);

    #pragma unroll
    for (int i = 0; i < 4; i++) {
        const int idx = tid + 256 * i;
        const size_t off = (size_t)row * D_MODEL + idx;
        const float o = resid[off] + (vals[i] - mu) * rs * gam[idx] + bet[idx];
        out[off] = o;
        if (out_r) out_r[off] = tf32r(o);
    }
}

// ---------------- launch -----------------------------------------------------
extern "C" void kernel_launch(void* const* d_in, const int* in_sizes, int n_in,
                              void* d_out, int out_size)
{
    const float* x     = (const float*)d_in[0];
    const float* wq    = (const float*)d_in[1];
    const float* bq    = (const float*)d_in[2];
    const float* wk    = (const float*)d_in[3];
    const float* bk    = (const float*)d_in[4];
    const float* wv    = (const float*)d_in[5];
    const float* bv    = (const float*)d_in[6];
    const float* wo    = (const float*)d_in[7];
    const float* ln1_g = (const float*)d_in[8];
    const float* ln1_b = (const float*)d_in[9];
    const float* w1    = (const float*)d_in[10];
    const float* b1    = (const float*)d_in[11];
    const float* w2    = (const float*)d_in[12];
    const float* ln2_g = (const float*)d_in[13];
    const float* ln2_b = (const float*)d_in[14];
    float* out = (float*)d_out;

    void *pQ, *pK, *pV, *pCTX, *pPRJ, *pX1, *pX1r, *pT, *pXr, *pH;
    void *pWTq, *pWTk, *pWTv, *pWTo, *pWT1, *pWT2;
    cudaGetSymbolAddress(&pQ,   g_Q);
    cudaGetSymbolAddress(&pK,   g_K);
    cudaGetSymbolAddress(&pV,   g_V);
    cudaGetSymbolAddress(&pCTX, g_CTX);
    cudaGetSymbolAddress(&pPRJ, g_PRJ);
    cudaGetSymbolAddress(&pX1,  g_X1);
    cudaGetSymbolAddress(&pX1r, g_X1r);
    cudaGetSymbolAddress(&pT,   g_T);
    cudaGetSymbolAddress(&pXr,  g_Xr);
    cudaGetSymbolAddress(&pH,   g_H);
    cudaGetSymbolAddress(&pWTq, g_WTq);
    cudaGetSymbolAddress(&pWTk, g_WTk);
    cudaGetSymbolAddress(&pWTv, g_WTv);
    cudaGetSymbolAddress(&pWTo, g_WTo);
    cudaGetSymbolAddress(&pWT1, g_WT1);
    cudaGetSymbolAddress(&pWT2, g_WT2);
    float* Q   = (float*)pQ;   float* K_  = (float*)pK;   float* V   = (float*)pV;
    float* CTX = (float*)pCTX; float* PRJ = (float*)pPRJ;
    float* X1  = (float*)pX1;  float* X1r = (float*)pX1r; float* T   = (float*)pT;
    float* Xr  = (float*)pXr;  float* H   = (float*)pH;
    float* WTq = (float*)pWTq; float* WTk = (float*)pWTk; float* WTv = (float*)pWTv;
    float* WTo = (float*)pWTo; float* WT1 = (float*)pWT1; float* WT2 = (float*)pWT2;

    const dim3 tblk(32, 8);
    transpose_rnd<<<dim3(D_MODEL/32, D_MODEL/32), tblk>>>(wq, WTq, D_MODEL, D_MODEL);
    transpose_rnd<<<dim3(D_MODEL/32, D_MODEL/32), tblk>>>(wk, WTk, D_MODEL, D_MODEL);
    transpose_rnd<<<dim3(D_MODEL/32, D_MODEL/32), tblk>>>(wv, WTv, D_MODEL, D_MODEL);
    transpose_rnd<<<dim3(D_MODEL/32, D_MODEL/32), tblk>>>(wo, WTo, D_MODEL, D_MODEL);
    transpose_rnd<<<dim3(DHID/32,    D_MODEL/32), tblk>>>(w1, WT1, D_MODEL, DHID);
    transpose_rnd<<<dim3(D_MODEL/32, DHID/32),    tblk>>>(w2, WT2, DHID, D_MODEL);

    const int nX = MROWS * D_MODEL;
    round_tf32<<<nX/1024, 256>>>(x, Xr, nX);

    const dim3 blk(256);
    const dim3 g1024(D_MODEL/128, MROWS/128);  // (8, 32)
    const dim3 g4096(DHID/128,    MROWS/128);  // (32, 32)

    // QKV projections (tf32 mma.sync)
    gemm_tc<<<g1024, blk>>>(Xr, WTq, bq, Q,  MROWS, D_MODEL, D_MODEL, 0, 0);
    gemm_tc<<<g1024, blk>>>(Xr, WTk, bk, K_, MROWS, D_MODEL, D_MODEL, 0, 0);
    gemm_tc<<<g1024, blk>>>(Xr, WTv, bv, V,  MROWS, D_MODEL, D_MODEL, 0, 0);

    // causal multi-head attention (fp32) -> CTX [B,S,H*dv] (tf32-rounded)
    attn_kernel<<<dim3(SEQ/64, BATCH*NHEADS), 64>>>(Q, K_, V, CTX);

    // out projection + LN + residual
    gemm_tc<<<g1024, blk>>>(CTX, WTo, nullptr, PRJ, MROWS, D_MODEL, D_MODEL, 0, 0);
    ln_res_kernel<<<MROWS, 256>>>(PRJ, x, ln1_g, ln1_b, X1, X1r);

    // FFN
    gemm_tc<<<g4096, blk>>>(X1r, WT1, b1, H, MROWS, DHID, D_MODEL, 1, 1);
    gemm_tc<<<g1024, blk>>>(H, WT2, nullptr, T, MROWS, D_MODEL, DHID, 0, 0);
    ln_res_kernel<<<MROWS, 256>>>(T, X1, ln2_g, ln2_b, out, nullptr);
}

// round 6
// speedup vs baseline: 3.5059x; 1.6820x over previous
#include <cuda_runtime.h>
#include <math.h>
#include <cstdint>

#define D_MODEL 1024
#define DHEAD   64
#define NHEADS  16
#define DHID    4096
#define BATCH   2
#define SEQ     2048
#define MROWS   (BATCH*SEQ)   // 4096
#define LN_EPS  1e-5f

// ---------------- scratch (device globals; no allocations allowed) ----------
__device__ float g_Q  [MROWS*D_MODEL];
__device__ float g_K  [MROWS*D_MODEL];
__device__ float g_V  [MROWS*D_MODEL];
__device__ float g_CTX[MROWS*D_MODEL];
__device__ float g_PRJ[MROWS*D_MODEL];
__device__ float g_X1 [MROWS*D_MODEL];
__device__ float g_X1r[MROWS*D_MODEL];
__device__ float g_T  [MROWS*D_MODEL];
__device__ float g_Xr [MROWS*D_MODEL];
__device__ float g_H  [(size_t)MROWS*DHID];
__device__ float g_WTq[D_MODEL*D_MODEL];
__device__ float g_WTk[D_MODEL*D_MODEL];
__device__ float g_WTv[D_MODEL*D_MODEL];
__device__ float g_WTo[D_MODEL*D_MODEL];
__device__ float g_WT1[(size_t)DHID*D_MODEL];
__device__ float g_WT2[(size_t)D_MODEL*DHID];

// ---------------- small asm helpers ------------------------------------------
__device__ __forceinline__ uint32_t smem_u32(const void* p) {
    uint32_t a;
    asm("{ .reg .u64 t; cvta.to.shared.u64 t, %1; cvt.u32.u64 %0, t; }" : "=r"(a) : "l"(p));
    return a;
}
__device__ __forceinline__ void cp_async16(uint32_t s, const void* g) {
    asm volatile("cp.async.cg.shared.global [%0], [%1], 16;" :: "r"(s), "l"(g));
}
#define CP_COMMIT() asm volatile("cp.async.commit_group;")
#define CP_WAIT(N)  asm volatile("cp.async.wait_group %0;" :: "n"(N))

__device__ __forceinline__ float tf32r(float x) {
    float y;
    asm("cvt.rna.tf32.f32 %0, %1;" : "=f"(y) : "f"(x));
    return y;
}
__device__ __forceinline__ void mma_tf32(float* d, const float* a, const float* b) {
    asm volatile(
        "mma.sync.aligned.m16n8k8.row.col.f32.tf32.tf32.f32 "
        "{%0,%1,%2,%3}, {%4,%5,%6,%7}, {%8,%9}, {%0,%1,%2,%3};"
        : "+f"(d[0]), "+f"(d[1]), "+f"(d[2]), "+f"(d[3])
        : "r"(__float_as_uint(a[0])), "r"(__float_as_uint(a[1])),
          "r"(__float_as_uint(a[2])), "r"(__float_as_uint(a[3])),
          "r"(__float_as_uint(b[0])), "r"(__float_as_uint(b[1])));
}

__device__ __forceinline__ float gelu_exact(float x) {
    return 0.5f * x * (1.0f + erff(x * 0.70710678118654752f));
}

// ---------------- tf32 mma.sync GEMM ------------------------------------------
#define BK   16
#define SROW 20

__global__ __launch_bounds__(256, 2)
void gemm_tc(const float* __restrict__ A, const float* __restrict__ BT,
             const float* __restrict__ bias, float* __restrict__ Cf,
             int M, int N, int K, int act, int round_out)
{
    __shared__ __align__(16) float As[2][128 * SROW];
    __shared__ __align__(16) float Bs[2][128 * SROW];

    const int tid  = threadIdx.x;
    const int wid  = tid >> 5;
    const int lane = tid & 31;
    const int wm   = wid >> 2;
    const int wn   = wid & 3;
    const int row0 = blockIdx.y * 128;
    const int col0 = blockIdx.x * 128;

    const uint32_t sA[2] = { smem_u32(As[0]), smem_u32(As[1]) };
    const uint32_t sB[2] = { smem_u32(Bs[0]), smem_u32(Bs[1]) };

    const int fr = lane >> 2;
    const int fc = lane & 3;

    float acc[4][4][4];
    #pragma unroll
    for (int i = 0; i < 4; i++)
        #pragma unroll
        for (int j = 0; j < 4; j++)
            #pragma unroll
            for (int q = 0; q < 4; q++) acc[i][j][q] = 0.0f;

    const int nChunks = K / BK;

    auto load_chunk = [&](int c, int st) {
        const int k0 = c * BK;
        #pragma unroll
        for (int i = 0; i < 2; i++) {
            const int u  = tid + i * 256;
            const int r  = u >> 2;
            const int kc = (u & 3) * 4;
            cp_async16(sA[st] + (uint32_t)(r * SROW + kc) * 4,
                       A  + (size_t)(row0 + r) * K + k0 + kc);
            cp_async16(sB[st] + (uint32_t)(r * SROW + kc) * 4,
                       BT + (size_t)(col0 + r) * K + k0 + kc);
        }
        CP_COMMIT();
    };

    load_chunk(0, 0);

    for (int c = 0; c < nChunks; c++) {
        const int st = c & 1;
        if (c + 1 < nChunks) { load_chunk(c + 1, st ^ 1); CP_WAIT(1); }
        else                 { CP_WAIT(0); }
        __syncthreads();

        const float* Ab = As[st];
        const float* Bb = Bs[st];

        #pragma unroll
        for (int ks = 0; ks < 2; ks++) {
            const int kk = ks * 8 + fc;
            float af[4][4], bfr[4][2];
            #pragma unroll
            for (int mt = 0; mt < 4; mt++) {
                const int r = wm * 64 + mt * 16 + fr;
                af[mt][0] = Ab[r * SROW + kk];
                af[mt][1] = Ab[(r + 8) * SROW + kk];
                af[mt][2] = Ab[r * SROW + kk + 4];
                af[mt][3] = Ab[(r + 8) * SROW + kk + 4];
            }
            #pragma unroll
            for (int nt = 0; nt < 4; nt++) {
                const int n = wn * 32 + nt * 8 + fr;
                bfr[nt][0] = Bb[n * SROW + ks * 8 + fc];
                bfr[nt][1] = Bb[n * SROW + ks * 8 + fc + 4];
            }
            #pragma unroll
            for (int mt = 0; mt < 4; mt++)
                #pragma unroll
                for (int nt = 0; nt < 4; nt++)
                    mma_tf32(acc[mt][nt], af[mt], bfr[nt]);
        }
        __syncthreads();
    }

    const int gr = lane >> 2;
    const int gc = (lane & 3) * 2;
    #pragma unroll
    for (int mt = 0; mt < 4; mt++) {
        #pragma unroll
        for (int nt = 0; nt < 4; nt++) {
            const int rA = row0 + wm * 64 + mt * 16 + gr;
            const int cA = col0 + wn * 32 + nt * 8 + gc;
            float b0 = 0.f, b1 = 0.f;
            if (bias) { b0 = bias[cA]; b1 = bias[cA + 1]; }
            float v00 = acc[mt][nt][0] + b0, v01 = acc[mt][nt][1] + b1;
            float v10 = acc[mt][nt][2] + b0, v11 = acc[mt][nt][3] + b1;
            if (act == 1) {
                v00 = gelu_exact(v00); v01 = gelu_exact(v01);
                v10 = gelu_exact(v10); v11 = gelu_exact(v11);
            }
            if (round_out) {
                v00 = tf32r(v00); v01 = tf32r(v01);
                v10 = tf32r(v10); v11 = tf32r(v11);
            }
            *(float2*)&Cf[(size_t)rA * N + cA]       = make_float2(v00, v01);
            *(float2*)&Cf[(size_t)(rA + 8) * N + cA] = make_float2(v10, v11);
        }
    }
}

// ---------------- fp32 -> tf32-rounded fp32 ----------------------------------
__global__ void round_tf32(const float* __restrict__ in, float* __restrict__ out, int n)
{
    const int i = (blockIdx.x * blockDim.x + threadIdx.x) * 4;
    if (i < n) {
        float4 v = *(const float4*)(in + i);
        v.x = tf32r(v.x); v.y = tf32r(v.y); v.z = tf32r(v.z); v.w = tf32r(v.w);
        *(float4*)(out + i) = v;
    }
}

// ---------------- transpose + tf32 round: W[K,N] f32 -> WT[N,K] --------------
__global__ void transpose_rnd(const float* __restrict__ W, float* __restrict__ WT,
                              int Kd, int Nd)
{
    __shared__ float t[32][33];
    const int bx = blockIdx.x * 32;
    const int by = blockIdx.y * 32;
    const int tx = threadIdx.x, ty = threadIdx.y;
    #pragma unroll
    for (int i = ty; i < 32; i += 8)
        t[i][tx] = W[(size_t)(by + i) * Nd + bx + tx];
    __syncthreads();
    #pragma unroll
    for (int i = ty; i < 32; i += 8)
        WT[(size_t)(bx + i) * Kd + by + tx] = tf32r(t[tx][i]);
}

// ---------------- tensor-core flash attention (tf32) -------------------------
// grid: (32, B*H), block 128 (4 warps). Block = 64 query rows; warp = 16 rows.
// Q,K,V already tf32-rounded.  Output CTX tf32-rounded.
#define KPAD 68
#define VPAD 72
#define ATTN_SMEM ((64*KPAD + 64*VPAD + 64*KPAD) * 4)

__global__ __launch_bounds__(128)
void attn_tc(const float* __restrict__ Qp, const float* __restrict__ Kp,
             const float* __restrict__ Vp, float* __restrict__ O)
{
    extern __shared__ float sm[];
    float* Ks = sm;                        // [64][KPAD]
    float* Vs = sm + 64 * KPAD;            // [64][VPAD]
    float* Ps = sm + 64 * KPAD + 64 * VPAD;// [64][KPAD]

    const int qt   = (int)gridDim.x - 1 - (int)blockIdx.x;  // long blocks first
    const int bh   = blockIdx.y;
    const int b    = bh >> 4;
    const int h    = bh & 15;
    const int tid  = threadIdx.x;
    const int wid  = tid >> 5;
    const int lane = tid & 31;
    const int r0   = lane >> 2;       // 0..7
    const int c0   = lane & 3;        // 0..3

    // --- Q fragments (16 rows per warp), scaled by 1/sqrt(64) -----------------
    float qa[8][4];
    {
        const size_t qbase = ((size_t)(b * SEQ + qt * 64 + wid * 16)) * D_MODEL + h * 64;
        #pragma unroll
        for (int ks = 0; ks < 8; ks++) {
            qa[ks][0] = Qp[qbase + (size_t)r0 * D_MODEL + ks * 8 + c0] * 0.125f;
            qa[ks][1] = Qp[qbase + (size_t)(r0 + 8) * D_MODEL + ks * 8 + c0] * 0.125f;
            qa[ks][2] = Qp[qbase + (size_t)r0 * D_MODEL + ks * 8 + c0 + 4] * 0.125f;
            qa[ks][3] = Qp[qbase + (size_t)(r0 + 8) * D_MODEL + ks * 8 + c0 + 4] * 0.125f;
        }
    }

    float o[8][4];
    #pragma unroll
    for (int nt = 0; nt < 8; nt++)
        #pragma unroll
        for (int q = 0; q < 4; q++) o[nt][q] = 0.0f;
    float mA = -1e30f, mB = -1e30f, lA = 0.0f, lB = 0.0f;

    const size_t kvbase = ((size_t)b * SEQ) * D_MODEL + h * 64;
    const int prow = wid * 16;   // this warp's P row block in Ps

    for (int kt = 0; kt <= qt; kt++) {
        // ---- cooperative K/V tile load (64x64 floats each) ------------------
        #pragma unroll
        for (int i = 0; i < 8; i++) {
            const int idx = i * 128 + tid;       // 0..1023
            const int r   = idx >> 4;
            const int c4  = (idx & 15) << 2;
            const size_t src = kvbase + (size_t)(kt * 64 + r) * D_MODEL + c4;
            *(float4*)&Ks[r * KPAD + c4] = *(const float4*)(Kp + src);
            *(float4*)&Vs[r * VPAD + c4] = *(const float4*)(Vp + src);
        }
        __syncthreads();

        // ---- S = Q K^T ------------------------------------------------------
        float s[8][4];
        #pragma unroll
        for (int nt = 0; nt < 8; nt++)
            #pragma unroll
            for (int q = 0; q < 4; q++) s[nt][q] = 0.0f;

        #pragma unroll
        for (int ks = 0; ks < 8; ks++) {
            #pragma unroll
            for (int nt = 0; nt < 8; nt++) {
                float bfr[2];
                bfr[0] = Ks[(nt * 8 + r0) * KPAD + ks * 8 + c0];
                bfr[1] = Ks[(nt * 8 + r0) * KPAD + ks * 8 + c0 + 4];
                mma_tf32(s[nt], qa[ks], bfr);
            }
        }

        // ---- causal mask (diagonal tile only) -------------------------------
        if (kt == qt) {
            const int rA = wid * 16 + r0;
            const int rB = rA + 8;
            #pragma unroll
            for (int nt = 0; nt < 8; nt++) {
                const int cc = nt * 8 + c0 * 2;
                if (cc     > rA) s[nt][0] = -1e30f;
                if (cc + 1 > rA) s[nt][1] = -1e30f;
                if (cc     > rB) s[nt][2] = -1e30f;
                if (cc + 1 > rB) s[nt][3] = -1e30f;
            }
        }

        // ---- online softmax -------------------------------------------------
        float tmA = -1e30f, tmB = -1e30f;
        #pragma unroll
        for (int nt = 0; nt < 8; nt++) {
            tmA = fmaxf(tmA, fmaxf(s[nt][0], s[nt][1]));
            tmB = fmaxf(tmB, fmaxf(s[nt][2], s[nt][3]));
        }
        tmA = fmaxf(tmA, __shfl_xor_sync(0xffffffffu, tmA, 1));
        tmA = fmaxf(tmA, __shfl_xor_sync(0xffffffffu, tmA, 2));
        tmB = fmaxf(tmB, __shfl_xor_sync(0xffffffffu, tmB, 1));
        tmB = fmaxf(tmB, __shfl_xor_sync(0xffffffffu, tmB, 2));

        const float mnA = fmaxf(mA, tmA);
        const float mnB = fmaxf(mB, tmB);
        const float cA = __expf(mA - mnA);
        const float cB = __expf(mB - mnB);
        lA *= cA; lB *= cB;
        #pragma unroll
        for (int nt = 0; nt < 8; nt++) {
            o[nt][0] *= cA; o[nt][1] *= cA;
            o[nt][2] *= cB; o[nt][3] *= cB;
        }

        float sumA = 0.0f, sumB = 0.0f;
        #pragma unroll
        for (int nt = 0; nt < 8; nt++) {
            const float p0 = __expf(s[nt][0] - mnA);
            const float p1 = __expf(s[nt][1] - mnA);
            const float p2 = __expf(s[nt][2] - mnB);
            const float p3 = __expf(s[nt][3] - mnB);
            sumA += p0 + p1;
            sumB += p2 + p3;
            *(float2*)&Ps[(prow + r0) * KPAD + nt * 8 + c0 * 2]     = make_float2(tf32r(p0), tf32r(p1));
            *(float2*)&Ps[(prow + r0 + 8) * KPAD + nt * 8 + c0 * 2] = make_float2(tf32r(p2), tf32r(p3));
        }
        sumA += __shfl_xor_sync(0xffffffffu, sumA, 1);
        sumA += __shfl_xor_sync(0xffffffffu, sumA, 2);
        sumB += __shfl_xor_sync(0xffffffffu, sumB, 1);
        sumB += __shfl_xor_sync(0xffffffffu, sumB, 2);
        lA += sumA; lB += sumB;
        mA = mnA; mB = mnB;

        __syncwarp();

        // ---- O += P V -------------------------------------------------------
        #pragma unroll
        for (int ks = 0; ks < 8; ks++) {
            float af[4];
            af[0] = Ps[(prow + r0) * KPAD + ks * 8 + c0];
            af[1] = Ps[(prow + r0 + 8) * KPAD + ks * 8 + c0];
            af[2] = Ps[(prow + r0) * KPAD + ks * 8 + c0 + 4];
            af[3] = Ps[(prow + r0 + 8) * KPAD + ks * 8 + c0 + 4];
            #pragma unroll
            for (int nt = 0; nt < 8; nt++) {
                float bfr[2];
                bfr[0] = Vs[(ks * 8 + c0) * VPAD + nt * 8 + r0];
                bfr[1] = Vs[(ks * 8 + c0 + 4) * VPAD + nt * 8 + r0];
                mma_tf32(o[nt], af, bfr);
            }
        }
        __syncthreads();
    }

    // ---- epilogue: normalize + tf32-round + store to CTX --------------------
    const float invA = 1.0f / lA;
    const float invB = 1.0f / lB;
    const size_t obase = ((size_t)(b * SEQ + qt * 64 + wid * 16)) * D_MODEL + h * 64;
    #pragma unroll
    for (int nt = 0; nt < 8; nt++) {
        const int cc = nt * 8 + c0 * 2;
        *(float2*)&O[obase + (size_t)r0 * D_MODEL + cc] =
            make_float2(tf32r(o[nt][0] * invA), tf32r(o[nt][1] * invA));
        *(float2*)&O[obase + (size_t)(r0 + 8) * D_MODEL + cc] =
            make_float2(tf32r(o[nt][2] * invB), tf32r(o[nt][3] * invB));
    }
}

// ---------------- fused LayerNorm + residual add -----------------------------
__global__ void ln_res_kernel(const float* __restrict__ inp, const float* __restrict__ resid,
                              const float* __restrict__ gam, const float* __restrict__ bet,
                              float* __restrict__ out, float* __restrict__ out_r)
{
    const int row = blockIdx.x;
    const int tid = threadIdx.x;
    const float* v = inp + (size_t)row * D_MODEL;

    float vals[4];
    float s = 0.0f;
    #pragma unroll
    for (int i = 0; i < 4; i++) { vals[i] = v[tid + 256 * i]; s += vals[i]; }

    __shared__ float red1[8];
    __shared__ float red2[8];
    const int lane = tid & 31, w = tid >> 5;

    #pragma unroll
    for (int o = 16; o > 0; o >>= 1) s += __shfl_xor_sync(0xffffffffu, s, o);
    if (lane == 0) red1[w] = s;
    __syncthreads();
    float mu = 0.0f;
    #pragma unroll
    for (int i = 0; i < 8; i++) mu += red1[i];
    mu *= (1.0f / D_MODEL);

    float vs = 0.0f;
    #pragma unroll
    for (int i = 0; i < 4; i++) { float d = vals[i] - mu; vs += d * d; }
    #pragma unroll
    for (int o = 16; o > 0; o >>= 1) vs += __shfl_xor_sync(0xffffffffu, vs, o);
    if (lane == 0) red2[w] = vs;
    __syncthreads();
    float var = 0.0f;
    #pragma unroll
    for (int i = 0; i < 8; i++) var += red2[i];
    var *= (1.0f / D_MODEL);
    const float rs = rsqrtf(var + LN_EPS);

    #pragma unroll
    for (int i = 0; i < 4; i++) {
        const int idx = tid + 256 * i;
        const size_t off = (size_t)row * D_MODEL + idx;
        const float o = resid[off] + (vals[i] - mu) * rs * gam[idx] + bet[idx];
        out[off] = o;
        if (out_r) out_r[off] = tf32r(o);
    }
}

// ---------------- launch -----------------------------------------------------
extern "C" void kernel_launch(void* const* d_in, const int* in_sizes, int n_in,
                              void* d_out, int out_size)
{
    const float* x     = (const float*)d_in[0];
    const float* wq    = (const float*)d_in[1];
    const float* bq    = (const float*)d_in[2];
    const float* wk    = (const float*)d_in[3];
    const float* bk    = (const float*)d_in[4];
    const float* wv    = (const float*)d_in[5];
    const float* bv    = (const float*)d_in[6];
    const float* wo    = (const float*)d_in[7];
    const float* ln1_g = (const float*)d_in[8];
    const float* ln1_b = (const float*)d_in[9];
    const float* w1    = (const float*)d_in[10];
    const float* b1    = (const float*)d_in[11];
    const float* w2    = (const float*)d_in[12];
    const float* ln2_g = (const float*)d_in[13];
    const float* ln2_b = (const float*)d_in[14];
    float* out = (float*)d_out;

    void *pQ, *pK, *pV, *pCTX, *pPRJ, *pX1, *pX1r, *pT, *pXr, *pH;
    void *pWTq, *pWTk, *pWTv, *pWTo, *pWT1, *pWT2;
    cudaGetSymbolAddress(&pQ,   g_Q);
    cudaGetSymbolAddress(&pK,   g_K);
    cudaGetSymbolAddress(&pV,   g_V);
    cudaGetSymbolAddress(&pCTX, g_CTX);
    cudaGetSymbolAddress(&pPRJ, g_PRJ);
    cudaGetSymbolAddress(&pX1,  g_X1);
    cudaGetSymbolAddress(&pX1r, g_X1r);
    cudaGetSymbolAddress(&pT,   g_T);
    cudaGetSymbolAddress(&pXr,  g_Xr);
    cudaGetSymbolAddress(&pH,   g_H);
    cudaGetSymbolAddress(&pWTq, g_WTq);
    cudaGetSymbolAddress(&pWTk, g_WTk);
    cudaGetSymbolAddress(&pWTv, g_WTv);
    cudaGetSymbolAddress(&pWTo, g_WTo);
    cudaGetSymbolAddress(&pWT1, g_WT1);
    cudaGetSymbolAddress(&pWT2, g_WT2);
    float* Q   = (float*)pQ;   float* K_  = (float*)pK;   float* V   = (float*)pV;
    float* CTX = (float*)pCTX; float* PRJ = (float*)pPRJ;
    float* X1  = (float*)pX1;  float* X1r = (float*)pX1r; float* T   = (float*)pT;
    float* Xr  = (float*)pXr;  float* H   = (float*)pH;
    float* WTq = (float*)pWTq; float* WTk = (float*)pWTk; float* WTv = (float*)pWTv;
    float* WTo = (float*)pWTo; float* WT1 = (float*)pWT1; float* WT2 = (float*)pWT2;

    cudaFuncSetAttribute(attn_tc, cudaFuncAttributeMaxDynamicSharedMemorySize, ATTN_SMEM);

    const dim3 tblk(32, 8);
    transpose_rnd<<<dim3(D_MODEL/32, D_MODEL/32), tblk>>>(wq, WTq, D_MODEL, D_MODEL);
    transpose_rnd<<<dim3(D_MODEL/32, D_MODEL/32), tblk>>>(wk, WTk, D_MODEL, D_MODEL);
    transpose_rnd<<<dim3(D_MODEL/32, D_MODEL/32), tblk>>>(wv, WTv, D_MODEL, D_MODEL);
    transpose_rnd<<<dim3(D_MODEL/32, D_MODEL/32), tblk>>>(wo, WTo, D_MODEL, D_MODEL);
    transpose_rnd<<<dim3(DHID/32,    D_MODEL/32), tblk>>>(w1, WT1, D_MODEL, DHID);
    transpose_rnd<<<dim3(D_MODEL/32, DHID/32),    tblk>>>(w2, WT2, DHID, D_MODEL);

    const int nX = MROWS * D_MODEL;
    round_tf32<<<nX/1024, 256>>>(x, Xr, nX);

    const dim3 blk(256);
    const dim3 g1024(D_MODEL/128, MROWS/128);  // (8, 32)
    const dim3 g4096(DHID/128,    MROWS/128);  // (32, 32)

    // QKV projections (tf32 mma.sync), outputs tf32-rounded for attention
    gemm_tc<<<g1024, blk>>>(Xr, WTq, bq, Q,  MROWS, D_MODEL, D_MODEL, 0, 1);
    gemm_tc<<<g1024, blk>>>(Xr, WTk, bk, K_, MROWS, D_MODEL, D_MODEL, 0, 1);
    gemm_tc<<<g1024, blk>>>(Xr, WTv, bv, V,  MROWS, D_MODEL, D_MODEL, 0, 1);

    // tensor-core causal attention -> CTX [B,S,H*dv] (tf32-rounded)
    attn_tc<<<dim3(SEQ/64, BATCH*NHEADS), 128, ATTN_SMEM>>>(Q, K_, V, CTX);

    // out projection + LN + residual
    gemm_tc<<<g1024, blk>>>(CTX, WTo, nullptr, PRJ, MROWS, D_MODEL, D_MODEL, 0, 0);
    ln_res_kernel<<<MROWS, 256>>>(PRJ, x, ln1_g, ln1_b, X1, X1r);

    // FFN
    gemm_tc<<<g4096, blk>>>(X1r, WT1, b1, H, MROWS, DHID, D_MODEL, 1, 1);
    gemm_tc<<<g1024, blk>>>(H, WT2, nullptr, T, MROWS, D_MODEL, DHID, 0, 0);
    ln_res_kernel<<<MROWS, 256>>>(T, X1, ln2_g, ln2_b, out, nullptr);
}